// round 1
// baseline (speedup 1.0000x reference)
#include <cuda_runtime.h>
#include <cstdint>

#define NN 2048
#define KA 64
#define CAP 131072
#define NITER 10

// ---------------- static device scratch (allocation-free contract) ----------
__device__ int   g_cnt[2][NN];
__device__ int   g_rp[2][NN + 1];
__device__ int   g_ci[2][CAP];
__device__ float g_Nn[2][NN * KA];
__device__ float g_P[2][NN * KA];
__device__ float g_q[(size_t)NN * NN];
__device__ float g_Ht[(size_t)NN * NN];
__device__ float g_M[2][(size_t)NN * NN];

// ---------------- CSR build: count -> scan -> fill (deterministic order) ----
__global__ void count_rows(const float* __restrict__ A, int sel) {
    int gw   = (blockIdx.x * blockDim.x + threadIdx.x) >> 5;
    int lane = threadIdx.x & 31;
    if (gw >= NN) return;
    const float* row = A + (size_t)gw * NN;
    int c = 0;
    for (int j = lane; j < NN; j += 32) c += (row[j] != 0.0f);
#pragma unroll
    for (int o = 16; o; o >>= 1) c += __shfl_down_sync(0xffffffffu, c, o);
    if (lane == 0) g_cnt[sel][gw] = c;
}

__global__ void scan_rows(int sel) {
    __shared__ int s[NN];
    int t = threadIdx.x;  // 1024 threads, 2 elems each
    s[t] = g_cnt[sel][t];
    s[t + 1024] = g_cnt[sel][t + 1024];
    __syncthreads();
    for (int off = 1; off < NN; off <<= 1) {
        int a = (t >= off) ? s[t - off] : 0;
        int b = s[t + 1024 - off];
        __syncthreads();
        if (t >= off) s[t] += a;
        s[t + 1024] += b;
        __syncthreads();
    }
    g_rp[sel][t + 1] = s[t];
    g_rp[sel][t + 1025] = s[t + 1024];
    if (t == 0) g_rp[sel][0] = 0;
}

__global__ void fill_rows(const float* __restrict__ A, int sel) {
    int gw   = (blockIdx.x * blockDim.x + threadIdx.x) >> 5;
    int lane = threadIdx.x & 31;
    if (gw >= NN) return;
    const float* row = A + (size_t)gw * NN;
    int base = g_rp[sel][gw];
    for (int c0 = 0; c0 < NN; c0 += 32) {
        bool p = (row[c0 + lane] != 0.0f);
        unsigned m = __ballot_sync(0xffffffffu, p);
        if (p) {
            int idx = base + __popc(m & ((1u << lane) - 1u));
            if (idx < CAP) g_ci[sel][idx] = c0 + lane;
        }
        base += __popc(m);
    }
}

// ---------------- attribute normalization + P = A @ Nn ----------------------
__global__ void norm_rows(const float* __restrict__ Nin, int sel) {
    int row = blockIdx.x;
    int lane = threadIdx.x;  // 32 threads, 2 cols each
    size_t base = (size_t)row * KA;
    float a = Nin[base + lane];
    float b = Nin[base + 32 + lane];
    float ss = a * a + b * b;
#pragma unroll
    for (int o = 16; o; o >>= 1) ss += __shfl_xor_sync(0xffffffffu, ss, o);
    float nrm = sqrtf(ss);
    float inv = (nrm > 0.0f) ? (1.0f / nrm) : 0.0f;
    g_Nn[sel][base + lane] = a * inv;
    g_Nn[sel][base + 32 + lane] = b * inv;
}

__global__ void spmm_attr(int sel) {
    int row = blockIdx.x;
    int lane = threadIdx.x;  // 64 threads = KA
    float acc = 0.0f;
    int e0 = g_rp[sel][row], e1 = g_rp[sel][row + 1];
    for (int e = e0; e < e1; e++)
        acc += g_Nn[sel][(size_t)g_ci[sel][e] * KA + lane];
    g_P[sel][(size_t)row * KA + lane] = acc;
}

// ---------------- q = rsqrt(Nm*dm) * Nm, Nm = N1n N2n^T, dm = P1 P2^T -------
__global__ void q_kernel() {
    __shared__ float sA[16][65], sB[16][65], sC[16][65], sD[16][65];
    int tx = threadIdx.x, ty = threadIdx.y;
    int t = ty * 16 + tx;
    int r = t >> 4;
    int c = (t & 15) * 4;
    int gi = blockIdx.y * 16, gj = blockIdx.x * 16;
    float4 a4 = *(const float4*)&g_Nn[0][(size_t)(gi + r) * KA + c];
    float4 b4 = *(const float4*)&g_Nn[1][(size_t)(gj + r) * KA + c];
    float4 c4 = *(const float4*)&g_P[0][(size_t)(gi + r) * KA + c];
    float4 d4 = *(const float4*)&g_P[1][(size_t)(gj + r) * KA + c];
    sA[r][c] = a4.x; sA[r][c + 1] = a4.y; sA[r][c + 2] = a4.z; sA[r][c + 3] = a4.w;
    sB[r][c] = b4.x; sB[r][c + 1] = b4.y; sB[r][c + 2] = b4.z; sB[r][c + 3] = b4.w;
    sC[r][c] = c4.x; sC[r][c + 1] = c4.y; sC[r][c + 2] = c4.z; sC[r][c + 3] = c4.w;
    sD[r][c] = d4.x; sD[r][c + 1] = d4.y; sD[r][c + 2] = d4.z; sD[r][c + 3] = d4.w;
    __syncthreads();
    float nm = 0.0f, dm = 0.0f;
#pragma unroll
    for (int k = 0; k < KA; k++) {
        nm += sA[ty][k] * sB[tx][k];
        dm += sC[ty][k] * sD[tx][k];
    }
    float D = nm * dm;
    float dd = (D > 0.0f) ? (1.0f / sqrtf(D)) : 0.0f;
    g_q[(size_t)(gi + ty) * NN + (gj + tx)] = dd * nm;
}

// ---------------- Ht = H^T, M0 = q .* Ht ------------------------------------
__global__ void transpose_m0(const float* __restrict__ H) {
    __shared__ float tile[32][33];
    int x = blockIdx.x * 32 + threadIdx.x;
    int y0 = blockIdx.y * 32;
#pragma unroll
    for (int k = 0; k < 32; k += 8)
        tile[threadIdx.y + k][threadIdx.x] =
            H[(size_t)(y0 + threadIdx.y + k) * NN + x];
    __syncthreads();
    int ox = blockIdx.y * 32 + threadIdx.x;
    int oy0 = blockIdx.x * 32;
#pragma unroll
    for (int k = 0; k < 32; k += 8) {
        size_t idx = (size_t)(oy0 + threadIdx.y + k) * NN + ox;
        float v = tile[threadIdx.x][threadIdx.y + k];
        g_Ht[idx] = v;
        g_M[0][idx] = g_q[idx] * v;  // s0 = h  =>  M0 = q .* h
    }
}

// ---------------- fused iteration: S = A1 (q.*s) A2 ; s' ; M' ---------------
// block = one output row i. Stage 1: acc[c] = sum_{j in adj1(i)} M[j][c].
// Stage 2: S[i][j] = sum_{k in adj2(j)} acc[k]; s' = 0.18*Ht + 0.82*q*S;
//          M'[i][j] = q*s'. A2 symmetric => col adjacency == row adjacency.
__global__ void __launch_bounds__(256) iter_kernel(int par, float* __restrict__ sOut,
                                                   int writeS) {
    __shared__ float acc_s[NN];
    const float* __restrict__ Min = g_M[par];
    float* __restrict__ Mout = g_M[par ^ 1];
    int i = blockIdx.x;
    int tid = threadIdx.x;
    float acc[8];
#pragma unroll
    for (int u = 0; u < 8; u++) acc[u] = 0.0f;
    int b = g_rp[0][i], e = g_rp[0][i + 1];
    for (int p = b; p < e; p++) {
        const float* Mr = Min + (size_t)g_ci[0][p] * NN;
#pragma unroll
        for (int u = 0; u < 8; u++) acc[u] += Mr[tid + u * 256];
    }
#pragma unroll
    for (int u = 0; u < 8; u++) acc_s[tid + u * 256] = acc[u];
    __syncthreads();
    size_t base = (size_t)i * NN;
    for (int j = tid; j < NN; j += 256) {
        int b2 = g_rp[1][j], e2 = g_rp[1][j + 1];
        float sum = 0.0f;
        for (int t2 = b2; t2 < e2; t2++) sum += acc_s[g_ci[1][t2]];
        float qv = g_q[base + j];
        float sv = 0.18f * g_Ht[base + j] + 0.82f * (qv * sum);
        Mout[base + j] = qv * sv;
        if (writeS) sOut[base + j] = sv;
    }
}

// ---------------- launch ----------------------------------------------------
extern "C" void kernel_launch(void* const* d_in, const int* in_sizes, int n_in,
                              void* d_out, int out_size) {
    const float* A1 = (const float*)d_in[0];
    const float* A2 = (const float*)d_in[1];
    const float* N1 = (const float*)d_in[2];
    const float* N2 = (const float*)d_in[3];
    const float* H  = (const float*)d_in[4];
    float* out = (float*)d_out;

    count_rows<<<256, 256>>>(A1, 0);
    count_rows<<<256, 256>>>(A2, 1);
    scan_rows<<<1, 1024>>>(0);
    scan_rows<<<1, 1024>>>(1);
    fill_rows<<<256, 256>>>(A1, 0);
    fill_rows<<<256, 256>>>(A2, 1);

    norm_rows<<<NN, 32>>>(N1, 0);
    norm_rows<<<NN, 32>>>(N2, 1);
    spmm_attr<<<NN, 64>>>(0);
    spmm_attr<<<NN, 64>>>(1);

    q_kernel<<<dim3(128, 128), dim3(16, 16)>>>();
    transpose_m0<<<dim3(64, 64), dim3(32, 8)>>>(H);

    for (int it = 0; it < NITER; it++)
        iter_kernel<<<NN, 256>>>(it & 1, out, (it == NITER - 1) ? 1 : 0);
}

// round 2
// speedup vs baseline: 2.8262x; 2.8262x over previous
#include <cuda_runtime.h>
#include <cstdint>

#define NN 2048
#define KA 64
#define CAP 131072
#define NITER 10
#define RPB 4   // rows per block in iter kernel

// ---------------- static device scratch (allocation-free contract) ----------
__device__ int   g_cnt[2][NN];
__device__ int   g_rp[2][NN + 1];
__device__ int   g_ci[2][CAP];
__device__ float g_Nn[2][NN * KA];
__device__ float g_P[2][NN * KA];
__device__ float g_q[(size_t)NN * NN];
__device__ float g_Ht[(size_t)NN * NN];
__device__ float g_M[2][(size_t)NN * NN];

// ---------------- setup: count nnz per row + row-l2-normalize attrs ---------
// blocks 0..511: count (sel = b>>8, warp-per-row). blocks 512..1023: norm.
__global__ void setup_count_norm(const float* __restrict__ A1,
                                 const float* __restrict__ A2,
                                 const float* __restrict__ N1,
                                 const float* __restrict__ N2) {
    int b = blockIdx.x;
    int warp = threadIdx.x >> 5;
    int lane = threadIdx.x & 31;
    if (b < 512) {
        int sel = b >> 8;
        int row = ((b & 255) << 3) + warp;
        const float* A = sel ? A2 : A1;
        const float* r = A + (size_t)row * NN;
        int c = 0;
        for (int j = lane; j < NN; j += 32) c += (r[j] != 0.0f);
#pragma unroll
        for (int o = 16; o; o >>= 1) c += __shfl_down_sync(0xffffffffu, c, o);
        if (lane == 0) g_cnt[sel][row] = c;
    } else {
        int idx = ((b - 512) << 3) + warp;  // 0..4095
        int sel = idx >> 11;
        int row = idx & 2047;
        const float* Nin = sel ? N2 : N1;
        size_t base = (size_t)row * KA;
        float a = Nin[base + lane];
        float c2 = Nin[base + 32 + lane];
        float ss = a * a + c2 * c2;
#pragma unroll
        for (int o = 16; o; o >>= 1) ss += __shfl_xor_sync(0xffffffffu, ss, o);
        float nrm = sqrtf(ss);
        float inv = (nrm > 0.0f) ? (1.0f / nrm) : 0.0f;
        g_Nn[sel][base + lane] = a * inv;
        g_Nn[sel][base + 32 + lane] = c2 * inv;
    }
}

// ---------------- exclusive scan of row counts (one block per matrix) -------
__global__ void scan_rows_both() {
    __shared__ int s[NN];
    int sel = blockIdx.x;
    int t = threadIdx.x;  // 1024 threads, 2 elems each
    s[t] = g_cnt[sel][t];
    s[t + 1024] = g_cnt[sel][t + 1024];
    __syncthreads();
    for (int off = 1; off < NN; off <<= 1) {
        int a = (t >= off) ? s[t - off] : 0;
        int b = s[t + 1024 - off];
        __syncthreads();
        if (t >= off) s[t] += a;
        s[t + 1024] += b;
        __syncthreads();
    }
    g_rp[sel][t + 1] = s[t];
    g_rp[sel][t + 1025] = s[t + 1024];
    if (t == 0) g_rp[sel][0] = 0;
}

// ---------------- fill CSR column indices (deterministic order) -------------
__global__ void fill_rows_both(const float* __restrict__ A1,
                               const float* __restrict__ A2) {
    int b = blockIdx.x;
    int sel = b >> 8;
    int row = ((b & 255) << 3) + (threadIdx.x >> 5);
    int lane = threadIdx.x & 31;
    const float* A = sel ? A2 : A1;
    const float* r = A + (size_t)row * NN;
    int base = g_rp[sel][row];
    for (int c0 = 0; c0 < NN; c0 += 32) {
        bool p = (r[c0 + lane] != 0.0f);
        unsigned m = __ballot_sync(0xffffffffu, p);
        if (p) {
            int idx = base + __popc(m & ((1u << lane) - 1u));
            if (idx < CAP) g_ci[sel][idx] = c0 + lane;
        }
        base += __popc(m);
    }
}

// ---------------- P = A @ Nn (add-only SpMM over attrs) ---------------------
__global__ void spmm_attr_both() {
    int sel = blockIdx.x >> 11;
    int row = blockIdx.x & 2047;
    int lane = threadIdx.x;  // 64 threads = KA
    float acc = 0.0f;
    int e0 = g_rp[sel][row], e1 = g_rp[sel][row + 1];
    for (int e = e0; e < e1; e++)
        acc += g_Nn[sel][(size_t)g_ci[sel][e] * KA + lane];
    g_P[sel][(size_t)row * KA + lane] = acc;
}

// ---------------- q = rsqrt(Nm*dm)*Nm, fused Ht = H^T and M0 = q.*Ht --------
// 64x64 tile / block, 16x16 threads, 4x4 outputs per thread, phased SMEM.
__global__ void __launch_bounds__(256) q_m0_kernel(const float* __restrict__ H) {
    __shared__ float sX[64][65];
    __shared__ float sY[64][65];
    int tx = threadIdx.x, ty = threadIdx.y;
    int t = ty * 16 + tx;
    int gi = blockIdx.y * 64, gj = blockIdx.x * 64;
    int lr = t >> 4;          // 0..15 (row within pass)
    int lk = (t & 15) * 4;    // k chunk

    float nm[4][4], dm[4][4];

    // phase 1: Nm tile
#pragma unroll
    for (int pass = 0; pass < 4; pass++) {
        int r = lr + pass * 16;
        float4 a = *(const float4*)&g_Nn[0][(size_t)(gi + r) * KA + lk];
        float4 b = *(const float4*)&g_Nn[1][(size_t)(gj + r) * KA + lk];
        sX[r][lk] = a.x; sX[r][lk + 1] = a.y; sX[r][lk + 2] = a.z; sX[r][lk + 3] = a.w;
        sY[r][lk] = b.x; sY[r][lk + 1] = b.y; sY[r][lk + 2] = b.z; sY[r][lk + 3] = b.w;
    }
    __syncthreads();
#pragma unroll
    for (int r = 0; r < 4; r++)
#pragma unroll
        for (int c = 0; c < 4; c++) nm[r][c] = 0.0f;
    for (int k = 0; k < KA; k++) {
        float a[4], b[4];
#pragma unroll
        for (int r = 0; r < 4; r++) a[r] = sX[ty * 4 + r][k];
#pragma unroll
        for (int c = 0; c < 4; c++) b[c] = sY[tx * 4 + c][k];
#pragma unroll
        for (int r = 0; r < 4; r++)
#pragma unroll
            for (int c = 0; c < 4; c++) nm[r][c] += a[r] * b[c];
    }
    __syncthreads();

    // phase 2: dm tile (P1 P2^T)
#pragma unroll
    for (int pass = 0; pass < 4; pass++) {
        int r = lr + pass * 16;
        float4 a = *(const float4*)&g_P[0][(size_t)(gi + r) * KA + lk];
        float4 b = *(const float4*)&g_P[1][(size_t)(gj + r) * KA + lk];
        sX[r][lk] = a.x; sX[r][lk + 1] = a.y; sX[r][lk + 2] = a.z; sX[r][lk + 3] = a.w;
        sY[r][lk] = b.x; sY[r][lk + 1] = b.y; sY[r][lk + 2] = b.z; sY[r][lk + 3] = b.w;
    }
    __syncthreads();
#pragma unroll
    for (int r = 0; r < 4; r++)
#pragma unroll
        for (int c = 0; c < 4; c++) dm[r][c] = 0.0f;
    for (int k = 0; k < KA; k++) {
        float a[4], b[4];
#pragma unroll
        for (int r = 0; r < 4; r++) a[r] = sX[ty * 4 + r][k];
#pragma unroll
        for (int c = 0; c < 4; c++) b[c] = sY[tx * 4 + c][k];
#pragma unroll
        for (int r = 0; r < 4; r++)
#pragma unroll
            for (int c = 0; c < 4; c++) dm[r][c] += a[r] * b[c];
    }
    __syncthreads();

    // phase 3: H tile transposed: sY[j_local][i_local] = H[gj+j][gi+i]
#pragma unroll
    for (int pass = 0; pass < 4; pass++) {
        int r = lr + pass * 16;
        float4 h = *(const float4*)&H[(size_t)(gj + r) * NN + gi + lk];
        sY[r][lk] = h.x; sY[r][lk + 1] = h.y; sY[r][lk + 2] = h.z; sY[r][lk + 3] = h.w;
    }
    __syncthreads();

#pragma unroll
    for (int r = 0; r < 4; r++) {
        int i = gi + ty * 4 + r;
        size_t base = (size_t)i * NN + gj + tx * 4;
        float4 qv, hv, mv;
        float* qp = (float*)&qv;
        float* hp = (float*)&hv;
        float* mp = (float*)&mv;
#pragma unroll
        for (int c = 0; c < 4; c++) {
            float D = nm[r][c] * dm[r][c];
            float dd = (D > 0.0f) ? (1.0f / sqrtf(D)) : 0.0f;
            float q = dd * nm[r][c];
            float ht = sY[tx * 4 + c][ty * 4 + r];
            qp[c] = q;
            hp[c] = ht;
            mp[c] = q * ht;
        }
        *(float4*)&g_q[base] = qv;
        *(float4*)&g_Ht[base] = hv;
        *(float4*)&g_M[0][base] = mv;
    }
}

// ---------------- fused iteration: S = A1 (q.*s) A2 ; s' ; M' ---------------
// block = RPB output rows. Stage 1: acc_s[k*4+r] = sum_{p in adj1(i0+r)} M[p][k].
// Stage 2: per j, one index stream serves 4 rows via an LDS.128 gather.
__global__ void __launch_bounds__(256) iter_kernel(int par, float* __restrict__ sOut,
                                                   int writeS) {
    __shared__ float acc_s[NN * RPB];  // 32 KB, interleaved [k][r]
    const float* __restrict__ Min = g_M[par];
    float* __restrict__ Mout = g_M[par ^ 1];
    int i0 = blockIdx.x * RPB;
    int tid = threadIdx.x;

    // stage 1: gather adjacency-1 rows (float4 wide loads)
    const float4* __restrict__ Min4 = (const float4*)Min;
#pragma unroll
    for (int r = 0; r < RPB; r++) {
        float4 a0 = make_float4(0.f, 0.f, 0.f, 0.f);
        float4 a1 = make_float4(0.f, 0.f, 0.f, 0.f);
        int b = g_rp[0][i0 + r], e = g_rp[0][i0 + r + 1];
        for (int p = b; p < e; p++) {
            const float4* Mr = Min4 + (size_t)g_ci[0][p] * (NN / 4);
            float4 v0 = Mr[tid];
            float4 v1 = Mr[tid + 256];
            a0.x += v0.x; a0.y += v0.y; a0.z += v0.z; a0.w += v0.w;
            a1.x += v1.x; a1.y += v1.y; a1.z += v1.z; a1.w += v1.w;
        }
        int k0 = tid * 4;
        acc_s[(k0 + 0) * RPB + r] = a0.x;
        acc_s[(k0 + 1) * RPB + r] = a0.y;
        acc_s[(k0 + 2) * RPB + r] = a0.z;
        acc_s[(k0 + 3) * RPB + r] = a0.w;
        int k1 = (tid + 256) * 4;
        acc_s[(k1 + 0) * RPB + r] = a1.x;
        acc_s[(k1 + 1) * RPB + r] = a1.y;
        acc_s[(k1 + 2) * RPB + r] = a1.z;
        acc_s[(k1 + 3) * RPB + r] = a1.w;
    }
    __syncthreads();

    // stage 2: per output column j, gather adjacency-2 once for all RPB rows
    const float4* __restrict__ acc4 = (const float4*)acc_s;
    for (int j = tid; j < NN; j += 256) {
        int b2 = g_rp[1][j], e2 = g_rp[1][j + 1];
        float4 sum = make_float4(0.f, 0.f, 0.f, 0.f);
        for (int p = b2; p < e2; p++) {
            float4 v = acc4[g_ci[1][p]];
            sum.x += v.x; sum.y += v.y; sum.z += v.z; sum.w += v.w;
        }
        float S[RPB] = {sum.x, sum.y, sum.z, sum.w};
#pragma unroll
        for (int r = 0; r < RPB; r++) {
            size_t idx = (size_t)(i0 + r) * NN + j;
            float qv = g_q[idx];
            float sv = 0.18f * g_Ht[idx] + 0.82f * (qv * S[r]);
            Mout[idx] = qv * sv;
            if (writeS) sOut[idx] = sv;
        }
    }
}

// ---------------- launch ----------------------------------------------------
extern "C" void kernel_launch(void* const* d_in, const int* in_sizes, int n_in,
                              void* d_out, int out_size) {
    const float* A1 = (const float*)d_in[0];
    const float* A2 = (const float*)d_in[1];
    const float* N1 = (const float*)d_in[2];
    const float* N2 = (const float*)d_in[3];
    const float* H  = (const float*)d_in[4];
    float* out = (float*)d_out;

    setup_count_norm<<<1024, 256>>>(A1, A2, N1, N2);   // launch 1
    scan_rows_both<<<2, 1024>>>();                     // launch 2
    fill_rows_both<<<512, 256>>>(A1, A2);              // launch 3
    spmm_attr_both<<<4096, 64>>>();                    // launch 4
    q_m0_kernel<<<dim3(32, 32), dim3(16, 16)>>>(H);    // launch 5

    for (int it = 0; it < NITER; it++)                 // launches 6..15
        iter_kernel<<<NN / RPB, 256>>>(it & 1, out, (it == NITER - 1) ? 1 : 0);
}